// round 1
// baseline (speedup 1.0000x reference)
#include <cuda_runtime.h>

// Problem constants
#define Bn 16
#define Cc 128
#define Hh 64
#define Ww 64

// Tiling
constexpr int CO_T = 32;   // output channels per block
constexpr int H_T  = 4;    // output rows per block
constexpr int W_T  = 64;   // output cols per block (full width)
constexpr int CI_T = 8;    // input-channel chunk

constexpr int IN_H     = H_T + 2;   // 6 (halo)
constexpr int IN_W     = W_T + 2;   // 66 (halo)
constexpr int IN_W_PAD = 68;        // pad so rows are 16B-aligned & f4 strip loads stay in-bounds
constexpr int W_PAD    = 33;        // pad co dim to kill store bank conflicts

__global__ __launch_bounds__(256, 4)
void resconv_kernel(const float* __restrict__ inp,
                    const float* __restrict__ wgt,
                    float* __restrict__ out)
{
    __shared__ float s_in[CI_T][IN_H][IN_W_PAD];
    __shared__ float s_w[CI_T][9][W_PAD];

    const int tid = threadIdx.x;
    const int tw  = tid & 7;          // 0..7 : w-group (8 outputs each)
    const int th  = (tid >> 3) & 3;   // 0..3 : output row within tile
    const int tco = tid >> 5;         // 0..7 : co-group (4 channels each)

    const int h0  = blockIdx.x * H_T;
    const int co0 = blockIdx.y * CO_T;
    const int b   = blockIdx.z;

    const float* inp_b = inp + (size_t)b * Cc * Hh * Ww;
    const float* wgt_b = wgt + (size_t)b * Cc * Cc * 9;

    float acc[4][8];
#pragma unroll
    for (int c = 0; c < 4; c++)
#pragma unroll
        for (int x = 0; x < 8; x++) acc[c][x] = 0.f;

    for (int ci0 = 0; ci0 < Cc; ci0 += CI_T) {
        // ---- stage input halo tile: CI_T x 6 x 66 valid (3168 elems) ----
        for (int idx = tid; idx < CI_T * IN_H * IN_W; idx += 256) {
            int ci  = idx / (IN_H * IN_W);
            int rem = idx - ci * (IN_H * IN_W);
            int lh  = rem / IN_W;
            int lw  = rem - lh * IN_W;
            int gh  = h0 + lh - 1;
            int gw  = lw - 1;
            float v = 0.f;
            if ((unsigned)gh < (unsigned)Hh && (unsigned)gw < (unsigned)Ww)
                v = inp_b[((size_t)(ci0 + ci) * Hh + gh) * Ww + gw];
            s_in[ci][lh][lw] = v;
        }
        // ---- stage weights: CO_T x CI_T x 9 = 2304 elems, layout [ci][k][co] ----
        for (int idx = tid; idx < CO_T * CI_T * 9; idx += 256) {
            int co  = idx / (CI_T * 9);
            int rem = idx - co * (CI_T * 9);
            int ci  = rem / 9;
            int k   = rem - ci * 9;
            s_w[ci][k][co] = wgt_b[(((size_t)(co0 + co) * Cc) + (ci0 + ci)) * 9 + k];
        }
        __syncthreads();

        // ---- compute ----
#pragma unroll 2
        for (int ci = 0; ci < CI_T; ci++) {
#pragma unroll
            for (int kh = 0; kh < 3; kh++) {
                const float* row = &s_in[ci][th + kh][tw * 8];
                float4 q0 = *(const float4*)(row);
                float4 q1 = *(const float4*)(row + 4);
                float4 q2 = *(const float4*)(row + 8);
                float strip[12] = {q0.x, q0.y, q0.z, q0.w,
                                   q1.x, q1.y, q1.z, q1.w,
                                   q2.x, q2.y, q2.z, q2.w};
#pragma unroll
                for (int kw = 0; kw < 3; kw++) {
                    float wv[4];
#pragma unroll
                    for (int c = 0; c < 4; c++)
                        wv[c] = s_w[ci][kh * 3 + kw][tco * 4 + c];
#pragma unroll
                    for (int c = 0; c < 4; c++)
#pragma unroll
                        for (int x = 0; x < 8; x++)
                            acc[c][x] = fmaf(wv[c], strip[x + kw], acc[c][x]);
                }
            }
        }
        __syncthreads();
    }

    // ---- epilogue: out = input + conv ----
    const int h = h0 + th;
#pragma unroll
    for (int c = 0; c < 4; c++) {
        int co = co0 + tco * 4 + c;
        const float* ip = inp_b + ((size_t)co * Hh + h) * Ww + tw * 8;
        float*       op = out + (((size_t)b * Cc + co) * Hh + h) * Ww + tw * 8;
        float4 r0 = *(const float4*)ip;
        float4 r1 = *(const float4*)(ip + 4);
        float4 o0, o1;
        o0.x = r0.x + acc[c][0];
        o0.y = r0.y + acc[c][1];
        o0.z = r0.z + acc[c][2];
        o0.w = r0.w + acc[c][3];
        o1.x = r1.x + acc[c][4];
        o1.y = r1.y + acc[c][5];
        o1.z = r1.z + acc[c][6];
        o1.w = r1.w + acc[c][7];
        *(float4*)op       = o0;
        *(float4*)(op + 4) = o1;
    }
}

extern "C" void kernel_launch(void* const* d_in, const int* in_sizes, int n_in,
                              void* d_out, int out_size)
{
    const float* inp = (const float*)d_in[0];   // [16,128,64,64] fp32
    const float* wgt = (const float*)d_in[1];   // [16,128,128,3,3] fp32
    float* out = (float*)d_out;                 // [16,128,64,64] fp32

    dim3 grid(Hh / H_T, Cc / CO_T, Bn);         // (16, 4, 16) = 1024 blocks
    resconv_kernel<<<grid, 256>>>(inp, wgt, out);
}

// round 3
// speedup vs baseline: 3.3747x; 3.3747x over previous
#include <cuda_runtime.h>
#include <cstdint>

#define Bn 16
#define Cc 128
#define Hh 64
#define Ww 64

// ---- scratch: weights pre-rounded to tf32 and transposed to [b][tap][co][ci] ----
__device__ uint32_t g_wt[(size_t)Bn * 9 * Cc * Cc];

__device__ __forceinline__ uint32_t f2tf32(float x) {
    uint32_t r;
    asm("cvt.rna.tf32.f32 %0, %1;" : "=r"(r) : "f"(x));
    return r;
}

__global__ void prep_w(const float* __restrict__ w) {
    int idx = blockIdx.x * blockDim.x + threadIdx.x;  // total 2359296
    int ci   = idx & 127;
    int co   = (idx >> 7) & 127;
    int rest = idx >> 14;      // b*9 + t
    int t    = rest % 9;
    int b    = rest / 9;
    float v = w[((size_t)(b * Cc + co) * Cc + ci) * 9 + t];
    g_wt[idx] = f2tf32(v);
}

// ---- main kernel ----
// smem layout (floats): X0 @0, X1 @3648, W0 @7296, W1 @21120  (total 34944 fl = 139776 B)
// X tile: [8 ci][6 rows][76 slots], ci-stride 456 (≡8 mod 32), row-stride 76; w=0 at slot 4.
// W tile: [9 tap][128 co][12], tap-stride 1536, co-stride 12 (conflict-free frag LDS).
#define XBUF_F   3648
#define WBUF_F   13824
#define X_CI     456
#define X_ROW    76
#define W_TAP    1536
#define W_CO     12

__device__ __forceinline__ uint32_t s2u(const void* p) {
    uint32_t a;
    asm("{ .reg .u64 t; cvta.to.shared.u64 t, %1; cvt.u32.u64 %0, t; }" : "=r"(a) : "l"(p));
    return a;
}

#define CP16(dst_u32, src_ptr) \
    asm volatile("cp.async.cg.shared.global [%0], [%1], 16;" :: "r"(dst_u32), "l"(src_ptr))

#define MMA_TF32(c, a, b0v, b1v)                                                  \
    asm volatile("mma.sync.aligned.m16n8k8.row.col.f32.tf32.tf32.f32 "            \
                 "{%0,%1,%2,%3}, {%4,%5,%6,%7}, {%8,%9}, {%0,%1,%2,%3};"          \
                 : "+f"((c)[0]), "+f"((c)[1]), "+f"((c)[2]), "+f"((c)[3])         \
                 : "r"((a)[0]), "r"((a)[1]), "r"((a)[2]), "r"((a)[3]),            \
                   "r"(b0v), "r"(b1v))

__global__ __launch_bounds__(512, 1)
void resconv_mma(const float* __restrict__ inp, float* __restrict__ out)
{
    extern __shared__ float smf[];
    uint32_t* smu = (uint32_t*)smf;

    const int tid  = threadIdx.x;
    const int lane = tid & 31;
    const int wid  = tid >> 5;
    const int wm   = wid & 1;        // 0..1  -> co half (64)
    const int wn   = wid >> 1;       // 0..7  -> n group (32)
    const int lr   = lane >> 2;      // 0..7
    const int lc   = lane & 3;       // 0..3

    const int h0 = blockIdx.x * 4;
    const int b  = blockIdx.y;
    const float* inp_b = inp + (size_t)b * Cc * Hh * Ww;

    const uint32_t sbase = s2u(smf);

    // ---- zero X buffers once (halo zeros are loop-invariant) ----
    for (int i = tid; i < 2 * XBUF_F; i += 512) smf[i] = 0.f;
    __syncthreads();

    float acc[4][4][4];
#pragma unroll
    for (int i = 0; i < 4; i++)
#pragma unroll
        for (int j = 0; j < 4; j++)
#pragma unroll
            for (int k = 0; k < 4; k++) acc[i][j][k] = 0.f;

    // ---- staging helpers (inlined lambdas) ----
    auto stageX = [&](int ci0, int xoff) {
#pragma unroll
        for (int it = 0; it < 2; it++) {
            int idx = tid + it * 512;
            if (idx < 768) {
                int ci  = idx / 96;
                int rem = idx - ci * 96;
                int row = rem >> 4;
                int seg = rem & 15;
                int gh  = h0 + row - 1;
                if ((unsigned)gh < (unsigned)Hh) {
                    float4 v = *(const float4*)(inp_b + ((size_t)(ci0 + ci) * Hh + gh) * Ww + seg * 4);
                    uint4 u;
                    u.x = f2tf32(v.x); u.y = f2tf32(v.y);
                    u.z = f2tf32(v.z); u.w = f2tf32(v.w);
                    *(uint4*)(smu + xoff + ci * X_CI + row * X_ROW + 4 + seg * 4) = u;
                }
            }
        }
    };
    auto stageW = [&](int ci0, int woff) {
        const uint32_t* wsrc = g_wt + (size_t)b * 9 * Cc * Cc;
#pragma unroll
        for (int it = 0; it < 5; it++) {
            int idx = tid + it * 512;
            if (idx < 2304) {
                int half = idx & 1;
                int co   = (idx >> 1) & 127;
                int tap  = idx >> 8;
                const uint32_t* src = wsrc + ((size_t)tap * Cc + co) * Cc + ci0 + half * 4;
                uint32_t dst = sbase + (uint32_t)(woff + tap * W_TAP + co * W_CO + half * 4) * 4u;
                CP16(dst, src);
            }
        }
        asm volatile("cp.async.commit_group;" ::: "memory");
    };

    // ---- prologue: stage chunk 0 ----
    stageX(0, 0);
    stageW(0, 2 * XBUF_F);
    asm volatile("cp.async.wait_group 0;" ::: "memory");
    __syncthreads();

    for (int kc = 0; kc < 16; kc++) {
        const int cur = kc & 1;
        const int xoff = cur * XBUF_F;
        const int woff = 2 * XBUF_F + cur * WBUF_F;

        if (kc < 15) {
            stageX((kc + 1) * 8, (cur ^ 1) * XBUF_F);
            stageW((kc + 1) * 8, 2 * XBUF_F + (cur ^ 1) * WBUF_F);
        }

        // ---- compute on current buffers ----
#pragma unroll
        for (int kh = 0; kh < 3; kh++) {
#pragma unroll
            for (int kw = 0; kw < 3; kw++) {
                const int t = kh * 3 + kw;
                uint32_t a[4][4];
#pragma unroll
                for (int tm = 0; tm < 4; tm++) {
                    const int cob = wm * 64 + tm * 16 + lr;
                    const uint32_t* p = smu + woff + t * W_TAP + cob * W_CO + lc;
                    a[tm][0] = p[0];
                    a[tm][1] = p[8 * W_CO];
                    a[tm][2] = p[4];
                    a[tm][3] = p[8 * W_CO + 4];
                }
#pragma unroll
                for (int tn = 0; tn < 4; tn++) {
                    const int n0 = wn * 32 + tn * 8;
                    const int r  = n0 >> 6;
                    const int x  = (n0 & 63) + lr;
                    const uint32_t* q = smu + xoff + lc * X_CI + (r + kh) * X_ROW + x + kw + 3;
                    uint32_t b0 = q[0];
                    uint32_t b1 = q[4 * X_CI];
#pragma unroll
                    for (int tm = 0; tm < 4; tm++)
                        MMA_TF32(acc[tm][tn], a[tm], b0, b1);
                }
            }
        }

        asm volatile("cp.async.wait_group 0;" ::: "memory");
        __syncthreads();
    }

    // ---- epilogue: out = inp + conv ----
#pragma unroll
    for (int tm = 0; tm < 4; tm++) {
#pragma unroll
        for (int tn = 0; tn < 4; tn++) {
            const int n = wn * 32 + tn * 8 + lc * 2;
            const int h = h0 + (n >> 6);
            const int w = n & 63;
            const int co0 = wm * 64 + tm * 16 + lr;
#pragma unroll
            for (int half = 0; half < 2; half++) {
                const int co = co0 + half * 8;
                const size_t off = ((size_t)(b * Cc + co) * Hh + h) * Ww + w;
                float2 rv = *(const float2*)(inp + off);
                float2 ov;
                ov.x = rv.x + acc[tm][tn][half * 2 + 0];
                ov.y = rv.y + acc[tm][tn][half * 2 + 1];
                *(float2*)(out + off) = ov;
            }
        }
    }
}

extern "C" void kernel_launch(void* const* d_in, const int* in_sizes, int n_in,
                              void* d_out, int out_size)
{
    const float* inp = (const float*)d_in[0];   // [16,128,64,64]
    const float* wgt = (const float*)d_in[1];   // [16,128,128,3,3]
    float* out = (float*)d_out;

    prep_w<<<(Bn * 9 * Cc * Cc) / 512, 512>>>(wgt);

    const int smem_bytes = (2 * XBUF_F + 2 * WBUF_F) * 4;   // 139776
    cudaFuncSetAttribute(resconv_mma, cudaFuncAttributeMaxDynamicSharedMemorySize, smem_bytes);
    dim3 grid(Hh / 4, Bn);   // (16, 16) = 256 CTAs
    resconv_mma<<<grid, 512, smem_bytes>>>(inp, out);
}